// round 12
// baseline (speedup 1.0000x reference)
#include <cuda_runtime.h>
#include <stdint.h>

// Problem constants
#define BZ   32
#define SEQ  2048
#define D    768
#define P    16
#define PLACEHOLDER_ID 1
#define ROWS (BZ * SEQ)          // 65536
#define D4   (D / 4)             // 192 float4 per row

typedef unsigned long long ull;

__device__ __forceinline__ float4 ldg_policy(const float4* p, ull pol) {
    float4 v;
    asm volatile("ld.global.nc.L2::cache_hint.v4.f32 {%0,%1,%2,%3}, [%4], %5;"
                 : "=f"(v.x), "=f"(v.y), "=f"(v.z), "=f"(v.w)
                 : "l"(p), "l"(pol));
    return v;
}

// ---------------------------------------------------------------------------
// Champion shape with RPB doubled to 16: per warp, 16 back-to-back 128B-wide
// gather reads, then 16 back-to-back coalesced streaming stores -> fewer
// read/write turnarounds at the DRAM controller per unit data.
// 4096 blocks x 192 threads; block handles 16 consecutive rows of one batch
// row. Placeholder rows (~506/4096 blocks contain one) overwritten afterwards
// by the same threads (program order).
// ---------------------------------------------------------------------------
#define GTPB 192
#define RPB  16
#define GBLOCKS (ROWS / RPB)     // 4096

__global__ __launch_bounds__(GTPB)
void fused_prompt_embed_kernel(const int* __restrict__ input_ids,
                               const float4* __restrict__ emb,
                               const float4* __restrict__ prompt,
                               float4* __restrict__ out) {
    const int r0    = blockIdx.x * RPB;
    const int t     = threadIdx.x;
    const int batch = r0 >> 11;              // r0 / SEQ
    const int seq0  = r0 & (SEQ - 1);
    const int* rid  = input_ids + ((size_t)batch << 11);

    ull pol;
    asm volatile("createpolicy.fractional.L2::evict_last.b64 %0, 1.0;" : "=l"(pol));

    // 16 consecutive ids as four 16B loads (uniform per block)
    int ids[RPB];
#pragma unroll
    for (int q = 0; q < 4; q++) {
        int4 ii = __ldg((const int4*)(rid + seq0) + q);
        ids[4 * q + 0] = ii.x; ids[4 * q + 1] = ii.y;
        ids[4 * q + 2] = ii.z; ids[4 * q + 3] = ii.w;
    }

    // 16 independent back-to-back LDG.128 gathers (long read burst)
    float4 v[RPB];
#pragma unroll
    for (int i = 0; i < RPB; i++)
        v[i] = ldg_policy(emb + (size_t)ids[i] * D4 + t, pol);

    // 16 unconditional coalesced streaming stores (long write burst)
#pragma unroll
    for (int i = 0; i < RPB; i++)
        __stcs(out + (size_t)(r0 + i) * D4 + t, v[i]);

    bool anyph = false;
#pragma unroll
    for (int i = 0; i < RPB; i++)
        anyph |= (ids[i] == PLACEHOLDER_ID);
    if (!anyph) return;                      // block-uniform branch

    // ---- rare path: recover placeholder rank(s), overwrite those rows ----
    int cnt = 0;
    for (int j = t; j < seq0; j += GTPB)
        cnt += (__ldg(&rid[j]) == PLACEHOLDER_ID);

    __shared__ int s_sum;
    if (t == 0) s_sum = 0;
    __syncthreads();
#pragma unroll
    for (int off = 16; off > 0; off >>= 1)
        cnt += __shfl_down_sync(0xFFFFFFFFu, cnt, off);
    if ((t & 31) == 0) atomicAdd(&s_sum, cnt);
    __syncthreads();

    int rank = s_sum;                        // placeholders before seq0
#pragma unroll
    for (int i = 0; i < RPB; i++) {
        if (ids[i] == PLACEHOLDER_ID) {
            int r = rank < (P - 1) ? rank : (P - 1);
            __stcs(out + (size_t)(r0 + i) * D4 + t, __ldg(&prompt[r * D4 + t]));
            rank++;
        }
    }
}

// ---------------------------------------------------------------------------
extern "C" void kernel_launch(void* const* d_in, const int* in_sizes, int n_in,
                              void* d_out, int out_size) {
    const int*    input_ids = (const int*)d_in[0];
    const float4* emb       = (const float4*)d_in[1];
    const float4* prompt    = (const float4*)d_in[2];
    float4*       out       = (float4*)d_out;

    fused_prompt_embed_kernel<<<GBLOCKS, GTPB>>>(input_ids, emb, prompt, out);
}

// round 13
// speedup vs baseline: 1.0132x; 1.0132x over previous
#include <cuda_runtime.h>
#include <stdint.h>

// Problem constants
#define BZ   32
#define SEQ  2048
#define D    768
#define P    16
#define PLACEHOLDER_ID 1
#define ROWS (BZ * SEQ)          // 65536
#define D4   (D / 4)             // 192 float4 per row

typedef unsigned long long ull;

// LDG.128 gather with a dynamic L2 cache policy (evict_last); access pattern
// identical to plain __ldg (measured equal-or-better than all alternatives).
__device__ __forceinline__ float4 ldg_policy(const float4* p, ull pol) {
    float4 v;
    asm volatile("ld.global.nc.L2::cache_hint.v4.f32 {%0,%1,%2,%3}, [%4], %5;"
                 : "=f"(v.x), "=f"(v.y), "=f"(v.z), "=f"(v.w)
                 : "l"(p), "l"(pol));
    return v;
}

// ---------------------------------------------------------------------------
// FINAL champion kernel (53.3us end-to-end, kernel ~48.6us @ DRAM ~69%).
// 8192 blocks x 192 threads; block handles 8 consecutive rows of one batch
// row:
//  - 8 uniform ids via two LDG.128
//  - 8 independent back-to-back LDG.128 gathers (PLACEHOLDER_ID=1 is a valid
//    emb row -> unconditional, MLP=8)
//  - 8 unconditional coalesced streaming stores (evict_first)
//  - rare path (~494/8192 blocks): cooperative placeholder count recovers the
//    rank; the same threads overwrite their rows with prompt[rank] (program
//    order makes the earlier bogus store harmless).
// DRAM-bound at the ~70%-of-spec mixed random-read/stream-write plateau with
// compulsory-minimal traffic; MLP, occupancy, L2 policy, burst shaping, and
// write-through were all measured neutral or worse.
// ---------------------------------------------------------------------------
#define GTPB 192
#define RPB  8
#define GBLOCKS (ROWS / RPB)     // 8192

__global__ __launch_bounds__(GTPB)
void fused_prompt_embed_kernel(const int* __restrict__ input_ids,
                               const float4* __restrict__ emb,
                               const float4* __restrict__ prompt,
                               float4* __restrict__ out) {
    const int r0    = blockIdx.x * RPB;
    const int t     = threadIdx.x;
    const int batch = r0 >> 11;              // r0 / SEQ
    const int seq0  = r0 & (SEQ - 1);
    const int* rid  = input_ids + ((size_t)batch << 11);

    ull pol;
    asm volatile("createpolicy.fractional.L2::evict_last.b64 %0, 1.0;" : "=l"(pol));

    // 8 consecutive ids as two 16B loads (uniform per block)
    int4 ia = __ldg((const int4*)(rid + seq0));
    int4 ib = __ldg((const int4*)(rid + seq0) + 1);
    int ids[RPB] = { ia.x, ia.y, ia.z, ia.w, ib.x, ib.y, ib.z, ib.w };

    // 8 independent back-to-back LDG.128 gathers (MLP=8)
    float4 v[RPB];
#pragma unroll
    for (int i = 0; i < RPB; i++)
        v[i] = ldg_policy(emb + (size_t)ids[i] * D4 + t, pol);

    // Unconditional coalesced streaming stores
#pragma unroll
    for (int i = 0; i < RPB; i++)
        __stcs(out + (size_t)(r0 + i) * D4 + t, v[i]);

    bool anyph = false;
#pragma unroll
    for (int i = 0; i < RPB; i++)
        anyph |= (ids[i] == PLACEHOLDER_ID);
    if (!anyph) return;                      // block-uniform branch

    // ---- rare path: recover placeholder rank(s), overwrite those rows ----
    int cnt = 0;
    for (int j = t; j < seq0; j += GTPB)
        cnt += (__ldg(&rid[j]) == PLACEHOLDER_ID);

    __shared__ int s_sum;
    if (t == 0) s_sum = 0;
    __syncthreads();
#pragma unroll
    for (int off = 16; off > 0; off >>= 1)
        cnt += __shfl_down_sync(0xFFFFFFFFu, cnt, off);
    if ((t & 31) == 0) atomicAdd(&s_sum, cnt);
    __syncthreads();

    int rank = s_sum;                        // placeholders before seq0
#pragma unroll
    for (int i = 0; i < RPB; i++) {
        if (ids[i] == PLACEHOLDER_ID) {
            int r = rank < (P - 1) ? rank : (P - 1);
            __stcs(out + (size_t)(r0 + i) * D4 + t, __ldg(&prompt[r * D4 + t]));
            rank++;
        }
    }
}

// ---------------------------------------------------------------------------
extern "C" void kernel_launch(void* const* d_in, const int* in_sizes, int n_in,
                              void* d_out, int out_size) {
    const int*    input_ids = (const int*)d_in[0];
    const float4* emb       = (const float4*)d_in[1];
    const float4* prompt    = (const float4*)d_in[2];
    float4*       out       = (float4*)d_out;

    fused_prompt_embed_kernel<<<GBLOCKS, GTPB>>>(input_ids, emb, prompt, out);
}